// round 1
// baseline (speedup 1.0000x reference)
#include <cuda_runtime.h>
#include <cstdint>
#include <cstddef>

#define D 128
#define MAXN 100000
#define BM 64
#define KSTRIDE 65   // u64 stride for smem tiles [128][KSTRIDE]

typedef unsigned long long u64;

// Scratch: aggregated neighbor features (pre-projection). 100000*128 fp32 = 51.2 MB.
__device__ float g_agg[(size_t)MAXN * D];

// ---------------------------------------------------------------------------
// helpers: packed f32x2 math (sm_100+/sm_103a)
// ---------------------------------------------------------------------------
__device__ __forceinline__ u64 dup2(float f) {
    u64 r; unsigned u = __float_as_uint(f);
    asm("mov.b64 %0, {%1, %1};" : "=l"(r) : "r"(u));
    return r;
}
__device__ __forceinline__ void ffma2(u64& d, u64 a, u64 b) {
    asm("fma.rn.f32x2 %0, %1, %2, %0;" : "+l"(d) : "l"(a), "l"(b));
}
__device__ __forceinline__ float2 unpack2(u64 v) {
    unsigned lo, hi;
    asm("mov.b64 {%0, %1}, %2;" : "=r"(lo), "=r"(hi) : "l"(v));
    float2 r; r.x = __uint_as_float(lo); r.y = __uint_as_float(hi);
    return r;
}

// Detect whether an index buffer is int64 (vs silently-demoted int32).
// For int64 with values in [0, 100000), every odd 32-bit word is 0.
__device__ __forceinline__ bool detect64(const int* p) {
    unsigned o = 0;
    #pragma unroll
    for (int i = 0; i < 16; i++) o |= (unsigned)p[2 * i + 1];
    return o == 0u;
}

// ---------------------------------------------------------------------------
// Kernel 1: zero the aggregation buffer
// ---------------------------------------------------------------------------
__global__ void zero_agg_kernel(int n4) {
    int i = blockIdx.x * blockDim.x + threadIdx.x;
    if (i < n4) ((float4*)g_agg)[i] = make_float4(0.f, 0.f, 0.f, 0.f);
}

// ---------------------------------------------------------------------------
// Kernel 2: edge-parallel SpMM on raw x:  agg[dst] += w * x[src]
// One warp processes a batch of 32 edges; per edge: 512 B gather (float4/lane)
// + vector fp32 reduction (red.global.add.v4.f32) scatter.
// ---------------------------------------------------------------------------
__global__ void __launch_bounds__(256) spmm_kernel(
    const float* __restrict__ x,
    const int* __restrict__ src_raw,
    const int* __restrict__ dst_raw,
    const float* __restrict__ w,
    int E)
{
    const bool is64 = detect64(src_raw);   // src/dst share dtype
    const int lane = threadIdx.x & 31;
    const int warp = (blockIdx.x * blockDim.x + threadIdx.x) >> 5;
    const int base = warp * 32;
    if (base >= E) return;
    const int cnt = min(32, E - base);
    const int e = base + lane;

    int s = 0, dd = 0; float ww = 0.f;
    if (lane < cnt) {
        if (is64) {
            s  = (int)((const long long*)src_raw)[e];
            dd = (int)((const long long*)dst_raw)[e];
        } else {
            s  = src_raw[e];
            dd = dst_raw[e];
        }
        ww = w[e];
    }

    const float4* x4 = (const float4*)x;
    for (int i = 0; i < cnt; i++) {
        int   si = __shfl_sync(0xffffffffu, s,  i);
        int   di = __shfl_sync(0xffffffffu, dd, i);
        float wi = __shfl_sync(0xffffffffu, ww, i);
        float4 v = __ldg(&x4[(size_t)si * (D / 4) + lane]);
        v.x *= wi; v.y *= wi; v.z *= wi; v.w *= wi;
        float* p = g_agg + (size_t)di * D + lane * 4;
        asm volatile("red.global.add.v4.f32 [%0], {%1, %2, %3, %4};"
                     :: "l"(p), "f"(v.x), "f"(v.y), "f"(v.z), "f"(v.w)
                     : "memory");
    }
}

// ---------------------------------------------------------------------------
// Kernel 3: fused dual GEMM with shared accumulators:
//   out = agg @ W_nbrs + x @ W_self + bias
// Block: 64 rows x 128 cols (full). 256 threads, each computes a 4x8 micro-tile
// as 4x4 f32x2 accumulators. Smem tiles hold values pre-duplicated into f32x2
// pairs so the inner loop is pure LDS.64 + LDG.128 + FFMA(f32x2).
// ---------------------------------------------------------------------------
__global__ void __launch_bounds__(256) gemm_kernel(
    const float* __restrict__ x,
    const float* __restrict__ Wn,
    const float* __restrict__ Ws,
    const float* __restrict__ bias,
    float* __restrict__ out,
    int n)
{
    extern __shared__ u64 sm[];
    u64* s_a = sm;                    // agg tile, [k][row] duplicated pairs
    u64* s_x = sm + 128 * KSTRIDE;    // x   tile

    const int tid = threadIdx.x;
    const int row0 = blockIdx.x * BM;

    // Tile load: lanes walk consecutive k (coalesced gmem, conflict-free smem).
    for (int idx = tid; idx < BM * D; idx += 256) {
        int r = idx >> 7;        // 0..63
        int k = idx & 127;
        int gr = row0 + r;
        float av = 0.f, xv = 0.f;
        if (gr < n) {
            av = g_agg[(size_t)gr * D + k];
            xv = x[(size_t)gr * D + k];
        }
        s_a[k * KSTRIDE + r] = dup2(av);
        s_x[k * KSTRIDE + r] = dup2(xv);
    }
    __syncthreads();

    const int c0 = (tid & 15) * 8;   // 16 col groups of 8
    const int r0 = (tid >> 4) * 4;   // 16 row groups of 4

    u64 acc[4][4];
    #pragma unroll
    for (int r = 0; r < 4; r++)
        #pragma unroll
        for (int c = 0; c < 4; c++) acc[r][c] = 0ull;

    #pragma unroll 4
    for (int k = 0; k < 128; k++) {
        const ulonglong2* pn = (const ulonglong2*)(Wn + (size_t)k * D + c0);
        const ulonglong2* ps = (const ulonglong2*)(Ws + (size_t)k * D + c0);
        ulonglong2 n0 = __ldg(pn);     // cols c0..c3 of W_nbrs row k
        ulonglong2 n1 = __ldg(pn + 1); // cols c4..c7
        ulonglong2 t0 = __ldg(ps);
        ulonglong2 t1 = __ldg(ps + 1);
        #pragma unroll
        for (int r = 0; r < 4; r++) {
            u64 a  = s_a[k * KSTRIDE + r0 + r];
            u64 xx = s_x[k * KSTRIDE + r0 + r];
            ffma2(acc[r][0], a, n0.x); ffma2(acc[r][0], xx, t0.x);
            ffma2(acc[r][1], a, n0.y); ffma2(acc[r][1], xx, t0.y);
            ffma2(acc[r][2], a, n1.x); ffma2(acc[r][2], xx, t1.x);
            ffma2(acc[r][3], a, n1.y); ffma2(acc[r][3], xx, t1.y);
        }
    }

    float4 b0 = *(const float4*)(bias + c0);
    float4 b1 = *(const float4*)(bias + c0 + 4);

    #pragma unroll
    for (int r = 0; r < 4; r++) {
        int row = row0 + r0 + r;
        if (row >= n) continue;
        float2 p0 = unpack2(acc[r][0]);
        float2 p1 = unpack2(acc[r][1]);
        float2 p2 = unpack2(acc[r][2]);
        float2 p3 = unpack2(acc[r][3]);
        float4 o0 = make_float4(p0.x + b0.x, p0.y + b0.y, p1.x + b0.z, p1.y + b0.w);
        float4 o1 = make_float4(p2.x + b1.x, p2.y + b1.y, p3.x + b1.z, p3.y + b1.w);
        float4* op = (float4*)(out + (size_t)row * D + c0);
        op[0] = o0;
        op[1] = o1;
    }
}

// ---------------------------------------------------------------------------
// launch
// ---------------------------------------------------------------------------
extern "C" void kernel_launch(void* const* d_in, const int* in_sizes, int n_in,
                              void* d_out, int out_size) {
    const float* x    = (const float*)d_in[0];
    const int*   src  = (const int*)d_in[1];
    const int*   dst  = (const int*)d_in[2];
    const float* w    = (const float*)d_in[3];
    const float* Wn   = (const float*)d_in[4];
    const float* Ws   = (const float*)d_in[5];
    const float* bias = (const float*)d_in[6];
    float* out = (float*)d_out;

    const int n = in_sizes[0] / D;       // nodes
    const int E = in_sizes[3];           // edges (dtype-independent count)

    // 1) zero agg
    {
        int n4 = n * (D / 4);
        int blk = 256;
        zero_agg_kernel<<<(n4 + blk - 1) / blk, blk>>>(n4);
    }

    // 2) edge-parallel scatter-add
    {
        int nwarps = (E + 31) / 32;
        long long threads = (long long)nwarps * 32;
        int blk = 256;
        int grid = (int)((threads + blk - 1) / blk);
        spmm_kernel<<<grid, blk>>>(x, src, dst, w, E);
    }

    // 3) fused dual GEMM epilogue
    {
        size_t smem = 2ull * 128 * KSTRIDE * sizeof(u64);  // 133,120 B
        cudaFuncSetAttribute(gemm_kernel,
                             cudaFuncAttributeMaxDynamicSharedMemorySize,
                             (int)smem);
        int grid = (n + BM - 1) / BM;
        gemm_kernel<<<grid, 256, smem>>>(x, Wn, Ws, bias, out, n);
    }
}